// round 8
// baseline (speedup 1.0000x reference)
#include <cuda_runtime.h>
#include <math.h>

// Problem constants: B=16, K=16 steps, N=1024, D=256, L=8.  Rows = B*L = 128.
#define S_ELEMS (16*16*8*256)

// ---------------- scratch (allocation-free __device__ globals) ----------------
__device__ __align__(16) float g_slots[128*256];
__device__ __align__(16) float g_Mcomb[256*1024];   // [i][0:256]=Wq^T Wk*scale, [i][256:1024]=W_hh^T
__device__ __align__(16) float g_cpart[8*1024];     // 8 e-partials of [scale*bq@Wk | b_hh]
__device__ __align__(16) float g_M2[768*256];       // M2[c][j] = sum_d W_ih[c,d]*Wv[d,j]
__device__ __align__(16) float g_c2part[8*768];     // 8 e-partials of (W_ih@bv + b_ih)
__device__ __align__(16) float g_qtgh[128*1024];    // [row][0:256]=Qtilde, [256:1024]=gh
__device__ __align__(16) float g_escore[128*1024];  // exp(score - chunkmax)
__device__ __align__(16) float g_pmax[128*8];       // per-row per-chunk max
__device__ __align__(16) float g_psum[128*8];       // per-row per-chunk sum exp
__device__ __align__(16) float g_upart[8*128*256];  // 8 chunk-partials of expP@H
__device__ __align__(16) float g_gi[128*768];
__device__ __align__(16) float g_s2[128*256];
__device__ __align__(16) float g_h1[128*256];

__device__ __forceinline__ float sigm(float x) { return 1.f / (1.f + expf(-x)); }

// ================= generic 32x32-tile fp32 GEMM body =================
// AT: A is [Kd][lda] (use A^T).  BT=0: B is [Kd][ldb]; BT=1: B is [Ncols][ldb] (C=A@B^T).
// SUMB: 0 none, 1 plain bias, 8 sum-of-8-partials bias.
template<int AT, int BT, int RELU, int SUMB>
__device__ __forceinline__ void gemm_body(
    int m0, int c0,
    const float* __restrict__ A, int lda,
    const float* __restrict__ B, int ldb,
    const float* __restrict__ bias, int strideBias,
    float* __restrict__ C, int ldc, int Kd, float alpha)
{
    __shared__ float As[32][33];
    __shared__ __align__(16) float Bs[32][36];
    const int tid = threadIdx.x;
    const int row = tid & 31, cg = tid >> 5;
    float a0 = 0.f, a1 = 0.f, a2 = 0.f, a3 = 0.f;

    for (int k0 = 0; k0 < Kd; k0 += 32) {
        if (AT) {
            int r = tid & 31, e = tid >> 5;
            #pragma unroll
            for (int i = 0; i < 4; i++) {
                int ee = e + i * 8;
                As[r][ee] = A[(size_t)(k0 + ee) * lda + m0 + r];
            }
        } else {
            int e = tid & 31, r = tid >> 5;
            #pragma unroll
            for (int i = 0; i < 4; i++) {
                int rr = r + i * 8;
                As[rr][e] = A[(size_t)(m0 + rr) * lda + k0 + e];
            }
        }
        if (BT) {
            int e = tid & 31, c = tid >> 5;
            #pragma unroll
            for (int i = 0; i < 4; i++) {
                int cc = c + i * 8;
                Bs[e][cc] = B[(size_t)(c0 + cc) * ldb + k0 + e];
            }
        } else {
            int c = tid & 31, e = tid >> 5;
            #pragma unroll
            for (int i = 0; i < 4; i++) {
                int ee = e + i * 8;
                Bs[ee][c] = B[(size_t)(k0 + ee) * ldb + c0 + c];
            }
        }
        __syncthreads();
        #pragma unroll
        for (int e = 0; e < 32; e++) {
            float a = As[row][e];
            float4 b4 = *(const float4*)&Bs[e][cg * 4];
            a0 = fmaf(a, b4.x, a0); a1 = fmaf(a, b4.y, a1);
            a2 = fmaf(a, b4.z, a2); a3 = fmaf(a, b4.w, a3);
        }
        __syncthreads();
    }
    int cb = c0 + cg * 4;
    float v0 = a0 * alpha, v1 = a1 * alpha, v2 = a2 * alpha, v3 = a3 * alpha;
    if (SUMB == 1) {
        v0 += bias[cb]; v1 += bias[cb+1]; v2 += bias[cb+2]; v3 += bias[cb+3];
    } else if (SUMB == 8) {
        #pragma unroll
        for (int p = 0; p < 8; p++) {
            const float* bp = bias + (size_t)p * strideBias;
            v0 += bp[cb]; v1 += bp[cb+1]; v2 += bp[cb+2]; v3 += bp[cb+3];
        }
    }
    if (RELU) { v0 = fmaxf(v0,0.f); v1 = fmaxf(v1,0.f); v2 = fmaxf(v2,0.f); v3 = fmaxf(v3,0.f); }
    *(float4*)&C[(size_t)(m0 + row) * ldc + cb] = make_float4(v0, v1, v2, v3);
}

// ================= precompute (2 kernels) =================
// pre_misc: blockIdx.x dispatch. [0,128) init_slots | [128,896) mhh | [896,928) ccomb | [928,952) c2
__global__ void pre_misc(const float* __restrict__ eps, const float* __restrict__ mu,
                         const float* __restrict__ ls, const float* __restrict__ W_hh,
                         const float* __restrict__ bq, const float* __restrict__ Wk,
                         const float* __restrict__ b_hh, const float* __restrict__ W_ih,
                         const float* __restrict__ bv, const float* __restrict__ b_ih)
{
    const int bx = blockIdx.x, tid = threadIdx.x;
    if (bx < 128) {
        int i = bx * 256 + tid;
        int ld = i & 2047;
        g_slots[i] = mu[ld] + expf(ls[ld]) * eps[i];
    } else if (bx < 896) {
        int idx = (bx - 128) * 256 + tid;       // over 256x768
        int c = idx >> 8, k = idx & 255;
        g_Mcomb[k * 1024 + 256 + c] = W_hh[c * 256 + k];
    } else if (bx < 928) {
        int q = bx - 896;
        int p = q >> 2;                          // e-chunk 0..7
        int c = (q & 3) * 256 + tid;             // 0..1023
        if (c < 256) {
            int e0 = p * 32;
            float s = 0.f;
            #pragma unroll 8
            for (int e = 0; e < 32; e++) s = fmaf(bq[e0+e], Wk[(e0+e)*256 + c], s);
            g_cpart[p * 1024 + c] = s * 0.0625f;
        } else {
            g_cpart[p * 1024 + c] = (p == 0) ? b_hh[c - 256] : 0.f;
        }
    } else {
        int q = bx - 928;                        // 0..23
        int p = q / 3;
        int c = (q % 3) * 256 + tid;
        int e0 = p * 32;
        float s = (p == 0) ? b_ih[c] : 0.f;
        #pragma unroll 8
        for (int e = 0; e < 32; e++) s = fmaf(W_ih[c*256 + e0+e], bv[e0+e], s);
        g_c2part[p * 768 + c] = s;
    }
}

// pre_gemm: grid(8,32). by<8: Mcomb[:,0:256] = scale*Wq^T@Wk.  by>=8: M2 = W_ih@Wv.
__global__ void pre_gemm(const float* __restrict__ Wq, const float* __restrict__ Wk,
                         const float* __restrict__ W_ih, const float* __restrict__ Wv)
{
    if (blockIdx.y < 8)
        gemm_body<1,0,0,0>(blockIdx.y*32, blockIdx.x*32, Wq,256, Wk,256, nullptr,0,
                           g_Mcomb,1024, 256, 0.0625f);
    else
        gemm_body<0,0,0,0>((blockIdx.y-8)*32, blockIdx.x*32, W_ih,256, Wv,256, nullptr,0,
                           g_M2,256, 256, 1.f);
}

// ================= per-step kernels (5) =================
__global__ void k_qtgh() {      // [128 x 1024] = slots @ Mcomb + ccomb   grid(32,4)
    gemm_body<0,0,0,8>(blockIdx.y*32, blockIdx.x*32, g_slots,256, g_Mcomb,1024,
                       g_cpart,1024, g_qtgh,1024, 256, 1.f);
}

// Fused scores + chunk-local softmax + partial attn@H.  grid(8 nchunk, 16 b), 256 thr.
__global__ void scoresU_kernel(const float* __restrict__ H, int t)
{
    __shared__ __align__(16) float4 Qs4[8][64];
    __shared__ float Hs[128][68];
    __shared__ float attnS[8][128];
    __shared__ float redM[8][4], redS[8][4], mrow[8];
    const int b = blockIdx.y, chunk = blockIdx.x;
    const int n0 = chunk * 128;
    const int tid = threadIdx.x;
    const int nl = tid & 127, half = tid >> 7;
    const int lane = tid & 31, wId = tid >> 5;

    for (int i = tid; i < 512; i += 256)
        Qs4[i >> 6][i & 63] = ((const float4*)(g_qtgh + (size_t)(b*8 + (i>>6)) * 1024))[i & 63];

    const float* hb = H + ((size_t)(b * 16 + t) * 1024 + n0) * 256;
    float a[4] = {0.f, 0.f, 0.f, 0.f};

    for (int d0 = 0; d0 < 256; d0 += 64) {
        __syncthreads();
        {
            int c = tid & 63, r0 = tid >> 6;
            #pragma unroll
            for (int i = 0; i < 32; i++)
                Hs[r0 + i*4][c] = hb[(size_t)(r0 + i*4) * 256 + d0 + c];
        }
        __syncthreads();
        #pragma unroll
        for (int d = 0; d < 64; d += 4) {
            float4 h4 = *(const float4*)&Hs[nl][d];
            int qd = (d0 + d) >> 2;
            #pragma unroll
            for (int s = 0; s < 4; s++) {
                float4 q4 = Qs4[half*4 + s][qd];
                a[s] = fmaf(h4.x, q4.x, a[s]); a[s] = fmaf(h4.y, q4.y, a[s]);
                a[s] = fmaf(h4.z, q4.z, a[s]); a[s] = fmaf(h4.w, q4.w, a[s]);
            }
        }
    }
    // chunk-local max per slot
    #pragma unroll
    for (int s = 0; s < 4; s++) {
        float m = a[s];
        #pragma unroll
        for (int o = 16; o > 0; o >>= 1) m = fmaxf(m, __shfl_xor_sync(0xffffffffu, m, o));
        if (lane == 0) redM[half*4 + s][wId & 3] = m;
    }
    __syncthreads();
    if (tid < 8) {
        float m = fmaxf(fmaxf(redM[tid][0], redM[tid][1]), fmaxf(redM[tid][2], redM[tid][3]));
        mrow[tid] = m;
        g_pmax[(b*8 + tid) * 8 + chunk] = m;
    }
    __syncthreads();
    // exp values: to gmem (for Beta), smem (for phase2), and chunk sums
    #pragma unroll
    for (int s = 0; s < 4; s++) {
        float e = expf(a[s] - mrow[half*4 + s]);
        g_escore[(size_t)(b*8 + half*4 + s) * 1024 + n0 + nl] = e;
        attnS[half*4 + s][nl] = e;
        #pragma unroll
        for (int o = 16; o > 0; o >>= 1) e += __shfl_xor_sync(0xffffffffu, e, o);
        if (lane == 0) redS[half*4 + s][wId & 3] = e;
    }
    __syncthreads();
    if (tid < 8)
        g_psum[(b*8 + tid) * 8 + chunk] = redS[tid][0] + redS[tid][1] + redS[tid][2] + redS[tid][3];

    // phase 2: Upart[s][j] = sum_n expP[s][n] * H[n][j]   (H re-read from L1/L2)
    float acc[8] = {0.f,0.f,0.f,0.f,0.f,0.f,0.f,0.f};
    const float* hb2 = hb + tid;
    #pragma unroll 4
    for (int n = 0; n < 128; n++) {
        float hv = hb2[(size_t)n * 256];
        #pragma unroll
        for (int s = 0; s < 8; s++) acc[s] = fmaf(attnS[s][n], hv, acc[s]);
    }
    float* up = g_upart + (size_t)chunk * 128 * 256;
    #pragma unroll
    for (int s = 0; s < 8; s++) up[(b*8 + s) * 256 + tid] = acc[s];
}

// gi = (flash-weighted sum of upart) @ M2^T + c2.  grid(24,4), 256 thr.
__global__ void k_gi()
{
    __shared__ float As[32][33];
    __shared__ __align__(16) float Bs[32][36];
    __shared__ float sm_w[32][9];
    const int tid = threadIdx.x;
    const int m0 = blockIdx.y * 32, c0 = blockIdx.x * 32;
    const int row = tid & 31, cg = tid >> 5;

    if (tid < 32) {
        int r = m0 + tid;
        float m = g_pmax[r*8];
        #pragma unroll
        for (int c = 1; c < 8; c++) m = fmaxf(m, g_pmax[r*8 + c]);
        float S = 0.f;
        #pragma unroll
        for (int c = 0; c < 8; c++) S += g_psum[r*8 + c] * expf(g_pmax[r*8 + c] - m);
        float invS = 1.f / S;
        #pragma unroll
        for (int c = 0; c < 8; c++) sm_w[tid][c] = expf(g_pmax[r*8 + c] - m) * invS;
    }
    __syncthreads();

    float a0 = 0.f, a1 = 0.f, a2 = 0.f, a3 = 0.f;
    for (int k0 = 0; k0 < 256; k0 += 32) {
        {
            int e = tid & 31, r = tid >> 5;
            #pragma unroll
            for (int i = 0; i < 4; i++) {
                int rr = r + i * 8;
                size_t idx = (size_t)(m0 + rr) * 256 + k0 + e;
                float v = 0.f;
                #pragma unroll
                for (int p = 0; p < 8; p++)
                    v = fmaf(g_upart[idx + (size_t)p * 128*256], sm_w[rr][p], v);
                As[rr][e] = v;
            }
        }
        {
            int e = tid & 31, c = tid >> 5;
            #pragma unroll
            for (int i = 0; i < 4; i++) {
                int cc = c + i * 8;
                Bs[e][cc] = g_M2[(size_t)(c0 + cc) * 256 + k0 + e];
            }
        }
        __syncthreads();
        #pragma unroll
        for (int e = 0; e < 32; e++) {
            float a = As[row][e];
            float4 b4 = *(const float4*)&Bs[e][cg * 4];
            a0 = fmaf(a, b4.x, a0); a1 = fmaf(a, b4.y, a1);
            a2 = fmaf(a, b4.z, a2); a3 = fmaf(a, b4.w, a3);
        }
        __syncthreads();
    }
    int cb = c0 + cg * 4;
    float v0 = a0, v1 = a1, v2 = a2, v3 = a3;
    #pragma unroll
    for (int p = 0; p < 8; p++) {
        const float* bp = g_c2part + p * 768;
        v0 += bp[cb]; v1 += bp[cb+1]; v2 += bp[cb+2]; v3 += bp[cb+3];
    }
    *(float4*)&g_gi[(size_t)(m0 + row) * 768 + cb] = make_float4(v0, v1, v2, v3);
}

// ffn1 with fused GRU + Beta writer.  grid(8,4), 256 thr.
__global__ void ffn1_gru_kernel(const float* __restrict__ W1, const float* __restrict__ b1,
                                float* __restrict__ beta, int t)
{
    __shared__ float As[32][33];
    __shared__ __align__(16) float Bs[32][36];
    const int tid = threadIdx.x;
    const int m0 = blockIdx.y * 32, c0 = blockIdx.x * 32;
    const int row = tid & 31, cg = tid >> 5;

    // ---- Beta writer: block lid covers rows 4*lid..4*lid+3, all 1024 cols ----
    {
        int lid = blockIdx.y * 8 + blockIdx.x;   // 0..31
        #pragma unroll
        for (int rr = 0; rr < 4; rr++) {
            int r = lid * 4 + rr;
            float m = g_pmax[r*8];
            #pragma unroll
            for (int c = 1; c < 8; c++) m = fmaxf(m, g_pmax[r*8 + c]);
            float S = 0.f;
            #pragma unroll
            for (int c = 0; c < 8; c++) S += g_psum[r*8 + c] * expf(g_pmax[r*8 + c] - m);
            float invS = 1.f / S;
            float w = expf(g_pmax[r*8 + (tid >> 5)] - m) * invS;
            float4 e4 = ((const float4*)(g_escore + (size_t)r * 1024))[tid];
            int b = r >> 3, l = r & 7;
            ((float4*)(beta + (size_t)((b*16 + t) * 8 + l) * 1024))[tid] =
                make_float4(e4.x * w, e4.y * w, e4.z * w, e4.w * w);
        }
    }

    float a0 = 0.f, a1 = 0.f, a2 = 0.f, a3 = 0.f;
    for (int k0 = 0; k0 < 256; k0 += 32) {
        {
            int e = tid & 31, r = tid >> 5;
            #pragma unroll
            for (int i = 0; i < 4; i++) {
                int rr = r + i * 8;
                int g = m0 + rr, d = k0 + e;
                float gir = g_gi[g*768 + d], giz = g_gi[g*768 + 256 + d], gin = g_gi[g*768 + 512 + d];
                float ghr = g_qtgh[g*1024 + 256 + d], ghz = g_qtgh[g*1024 + 512 + d], ghn = g_qtgh[g*1024 + 768 + d];
                float rg = sigm(gir + ghr);
                float z  = sigm(giz + ghz);
                float nn = tanhf(gin + rg * ghn);
                float s2 = (1.f - z) * nn + z * g_slots[g*256 + d];
                As[rr][e] = s2;
                if (blockIdx.x == 0) g_s2[g*256 + d] = s2;
            }
        }
        {
            int e = tid & 31, c = tid >> 5;
            #pragma unroll
            for (int i = 0; i < 4; i++) {
                int cc = c + i * 8;
                Bs[e][cc] = W1[(size_t)(c0 + cc) * 256 + k0 + e];
            }
        }
        __syncthreads();
        #pragma unroll
        for (int e = 0; e < 32; e++) {
            float a = As[row][e];
            float4 b4 = *(const float4*)&Bs[e][cg * 4];
            a0 = fmaf(a, b4.x, a0); a1 = fmaf(a, b4.y, a1);
            a2 = fmaf(a, b4.z, a2); a3 = fmaf(a, b4.w, a3);
        }
        __syncthreads();
    }
    int cb = c0 + cg * 4;
    *(float4*)&g_h1[(size_t)(m0 + row) * 256 + cb] = make_float4(
        fmaxf(a0 + b1[cb],   0.f), fmaxf(a1 + b1[cb+1], 0.f),
        fmaxf(a2 + b1[cb+2], 0.f), fmaxf(a3 + b1[cb+3], 0.f));
}

// ffn2 + residual + LayerNorm fused.  grid(16), 256 thr; warp w owns row r0+w (full 256 cols).
__global__ void ffn2_ln_kernel(const float* __restrict__ W2, const float* __restrict__ b2,
                               const float* __restrict__ lg, const float* __restrict__ lb,
                               float* __restrict__ outS, int t)
{
    __shared__ float As[8][256];       // h1 rows
    __shared__ float Bs[256 * 33];     // W2 staged c-major, pitch 33 (conflict-free)
    const int tid = threadIdx.x;
    const int w = tid >> 5, lane = tid & 31;
    const int r0 = blockIdx.x * 8, row = r0 + w;

    for (int i = tid; i < 2048; i += 256)
        As[i >> 8][i & 255] = g_h1[(size_t)(r0 + (i >> 8)) * 256 + (i & 255)];

    float acc[8] = {0.f,0.f,0.f,0.f,0.f,0.f,0.f,0.f};
    for (int e0 = 0; e0 < 256; e0 += 32) {
        __syncthreads();
        for (int idx = tid; idx < 8192; idx += 256) {
            int c = idx >> 5, e = idx & 31;
            Bs[c * 33 + e] = W2[(size_t)c * 256 + e0 + e];
        }
        __syncthreads();
        #pragma unroll
        for (int e = 0; e < 32; e++) {
            float a = As[w][e0 + e];
            #pragma unroll
            for (int i = 0; i < 8; i++)
                acc[i] = fmaf(a, Bs[(lane + 32*i) * 33 + e], acc[i]);
        }
    }
    // residual + LN within the warp (row fully owned by this warp)
    float x[8], s = 0.f, q = 0.f;
    #pragma unroll
    for (int i = 0; i < 8; i++) {
        int c = lane + 32*i;
        x[i] = acc[i] + b2[c] + g_s2[(size_t)row * 256 + c];
        s += x[i]; q += x[i] * x[i];
    }
    #pragma unroll
    for (int o = 16; o > 0; o >>= 1) {
        s += __shfl_xor_sync(0xffffffffu, s, o);
        q += __shfl_xor_sync(0xffffffffu, q, o);
    }
    float mean = s * (1.f / 256.f);
    float var  = q * (1.f / 256.f) - mean * mean;
    float inv  = rsqrtf(var + 1e-5f);
    int b = row >> 3, l = row & 7;
    float* oS = outS + (size_t)((b * 16 + t) * 8 + l) * 256;
    #pragma unroll
    for (int i = 0; i < 8; i++) {
        int c = lane + 32*i;
        float y = (x[i] - mean) * inv * lg[c] + lb[c];
        g_slots[(size_t)row * 256 + c] = y;
        oS[c] = y;
    }
}

// ================= launcher =================
extern "C" void kernel_launch(void* const* d_in, const int* in_sizes, int n_in,
                              void* d_out, int out_size)
{
    const float* H    = (const float*)d_in[0];
    const float* eps  = (const float*)d_in[1];
    const float* mu   = (const float*)d_in[2];
    const float* ls   = (const float*)d_in[3];
    const float* Wq   = (const float*)d_in[4];
    const float* bq   = (const float*)d_in[5];
    const float* Wk   = (const float*)d_in[6];
    // d_in[7] = bk: row-constant in logits, cancels in softmax — provably unused.
    const float* Wv   = (const float*)d_in[8];
    const float* bv   = (const float*)d_in[9];
    const float* W_ih = (const float*)d_in[10];
    const float* b_ih = (const float*)d_in[11];
    const float* W_hh = (const float*)d_in[12];
    const float* b_hh = (const float*)d_in[13];
    const float* W1   = (const float*)d_in[14];
    const float* b1   = (const float*)d_in[15];
    const float* W2   = (const float*)d_in[16];
    const float* b2   = (const float*)d_in[17];
    const float* lng  = (const float*)d_in[18];
    const float* lnb  = (const float*)d_in[19];

    float* outS = (float*)d_out;
    float* outB = outS + S_ELEMS;

    pre_misc<<<952, 256>>>(eps, mu, ls, W_hh, bq, Wk, b_hh, W_ih, bv, b_ih);
    pre_gemm<<<dim3(8, 32), 256>>>(Wq, Wk, W_ih, Wv);

    for (int t = 0; t < 16; t++) {
        k_qtgh<<<dim3(32, 4), 256>>>();
        scoresU_kernel<<<dim3(8, 16), 256>>>(H, t);
        k_gi<<<dim3(24, 4), 256>>>();
        ffn1_gru_kernel<<<dim3(8, 4), 256>>>(W1, b1, outB, t);
        ffn2_ln_kernel<<<16, 256>>>(W2, b2, lng, lnb, outS, t);
    }
}

// round 9
// speedup vs baseline: 1.2978x; 1.2978x over previous
#include <cuda_runtime.h>
#include <math.h>

// B=16, K=16 steps, N=1024, D=256, L=8.  Rows = B*L = 128.  n-chunks: 16 x 64.
#define S_ELEMS (16*16*8*256)
#define QT_PLANE (128*1024)
#define GI_PLANE (128*768)
#define H1_PLANE (128*256)
#define UP_PLANE (128*256)

// ---------------- scratch ----------------
__device__ __align__(16) float g_slots[128*256];
__device__ __align__(16) float g_Mcomb[256*1024];   // [k][0:256]=Wq^T Wk*scale, [k][256:1024]=W_hh^T
__device__ __align__(16) float g_cpart[8*1024];     // 8 e-partials of [scale*bq@Wk | b_hh]
__device__ __align__(16) float g_M2[768*256];       // W_ih @ Wv
__device__ __align__(16) float g_c2part[8*768];     // 8 e-partials of (W_ih@bv + b_ih)
__device__ __align__(16) float g_qtgh2[2*QT_PLANE]; // 2 K-split partials of [Qt | gh]
__device__ __align__(16) float g_escore[128*1024];  // exp(score - chunkmax)
__device__ __align__(16) float g_pmax[128*16];
__device__ __align__(16) float g_psum[128*16];
__device__ __align__(16) float g_upart[16*UP_PLANE];// normalized attn@H partials per n-chunk
__device__ __align__(16) float g_U[128*256];
__device__ __align__(16) float g_gi2[2*GI_PLANE];   // 2 K-split partials of gi
__device__ __align__(16) float g_s2[128*256];
__device__ __align__(16) float g_h1p[2*H1_PLANE];   // 2 K-split partials of ffn1 pre-activation

__device__ __forceinline__ float sigm(float x) { return 1.f / (1.f + expf(-x)); }

// ============ 32x32-tile GEMM body (precompute only) ============
template<int AT, int BT, int SUMB>
__device__ __forceinline__ void gemm_body(
    int m0, int c0,
    const float* __restrict__ A, int lda,
    const float* __restrict__ B, int ldb,
    const float* __restrict__ bias, int strideBias,
    float* __restrict__ C, int ldc, int Kd, float alpha)
{
    __shared__ float As[32][33];
    __shared__ __align__(16) float Bs[32][36];
    const int tid = threadIdx.x;
    const int row = tid & 31, cg = tid >> 5;
    float a0 = 0.f, a1 = 0.f, a2 = 0.f, a3 = 0.f;
    for (int k0 = 0; k0 < Kd; k0 += 32) {
        if (AT) {
            int r = tid & 31, e = tid >> 5;
            #pragma unroll
            for (int i = 0; i < 4; i++) { int ee = e + i*8; As[r][ee] = A[(size_t)(k0+ee)*lda + m0 + r]; }
        } else {
            int e = tid & 31, r = tid >> 5;
            #pragma unroll
            for (int i = 0; i < 4; i++) { int rr = r + i*8; As[rr][e] = A[(size_t)(m0+rr)*lda + k0 + e]; }
        }
        if (BT) {
            int e = tid & 31, c = tid >> 5;
            #pragma unroll
            for (int i = 0; i < 4; i++) { int cc = c + i*8; Bs[e][cc] = B[(size_t)(c0+cc)*ldb + k0 + e]; }
        } else {
            int c = tid & 31, e = tid >> 5;
            #pragma unroll
            for (int i = 0; i < 4; i++) { int ee = e + i*8; Bs[ee][c] = B[(size_t)(k0+ee)*ldb + c0 + c]; }
        }
        __syncthreads();
        #pragma unroll
        for (int e = 0; e < 32; e++) {
            float a = As[row][e];
            float4 b4 = *(const float4*)&Bs[e][cg*4];
            a0 = fmaf(a,b4.x,a0); a1 = fmaf(a,b4.y,a1); a2 = fmaf(a,b4.z,a2); a3 = fmaf(a,b4.w,a3);
        }
        __syncthreads();
    }
    int cb = c0 + cg*4;
    float v0 = a0*alpha, v1 = a1*alpha, v2 = a2*alpha, v3 = a3*alpha;
    if (SUMB == 1) { v0 += bias[cb]; v1 += bias[cb+1]; v2 += bias[cb+2]; v3 += bias[cb+3]; }
    *(float4*)&C[(size_t)(m0+row)*ldc + cb] = make_float4(v0, v1, v2, v3);
}

// ================= precompute (2 kernels) =================
__global__ void pre_misc(const float* __restrict__ eps, const float* __restrict__ mu,
                         const float* __restrict__ ls, const float* __restrict__ W_hh,
                         const float* __restrict__ bq, const float* __restrict__ Wk,
                         const float* __restrict__ b_hh, const float* __restrict__ W_ih,
                         const float* __restrict__ bv, const float* __restrict__ b_ih)
{
    const int bx = blockIdx.x, tid = threadIdx.x;
    if (bx < 128) {
        int i = bx * 256 + tid;
        int ld = i & 2047;
        g_slots[i] = mu[ld] + expf(ls[ld]) * eps[i];
    } else if (bx < 896) {
        int idx = (bx - 128) * 256 + tid;       // 256x768
        int c = idx >> 8, k = idx & 255;
        g_Mcomb[k * 1024 + 256 + c] = W_hh[c * 256 + k];
    } else if (bx < 928) {
        int q = bx - 896;
        int p = q >> 2;
        int c = (q & 3) * 256 + tid;
        if (c < 256) {
            int e0 = p * 32;
            float s = 0.f;
            #pragma unroll 8
            for (int e = 0; e < 32; e++) s = fmaf(bq[e0+e], Wk[(e0+e)*256 + c], s);
            g_cpart[p * 1024 + c] = s * 0.0625f;
        } else {
            g_cpart[p * 1024 + c] = (p == 0) ? b_hh[c - 256] : 0.f;
        }
    } else {
        int q = bx - 928;
        int p = q / 3;
        int c = (q % 3) * 256 + tid;
        int e0 = p * 32;
        float s = (p == 0) ? b_ih[c] : 0.f;
        #pragma unroll 8
        for (int e = 0; e < 32; e++) s = fmaf(W_ih[c*256 + e0+e], bv[e0+e], s);
        g_c2part[p * 768 + c] = s;
    }
}

__global__ void pre_gemm(const float* __restrict__ Wq, const float* __restrict__ Wk,
                         const float* __restrict__ W_ih, const float* __restrict__ Wv)
{
    if (blockIdx.y < 8)
        gemm_body<1,0,0>(blockIdx.y*32, blockIdx.x*32, Wq,256, Wk,256, nullptr,0,
                         g_Mcomb,1024, 256, 0.0625f);
    else
        gemm_body<0,0,0>((blockIdx.y-8)*32, blockIdx.x*32, W_ih,256, Wv,256, nullptr,0,
                         g_M2,256, 256, 1.f);
}

// ================= per-step kernels (7) =================

// qtgh partials: grid (32 colT, 8 rowT, 2 ksplit), 128 thr, tile 16x32.
__global__ void k_qtgh()
{
    __shared__ float As[16][33];
    __shared__ __align__(16) float Bs[32][36];
    const int tid = threadIdx.x;
    const int m0 = blockIdx.y * 16, c0 = blockIdx.x * 32, kb = blockIdx.z * 128;
    const int row = tid & 15, cg = tid >> 4;
    float a0=0.f, a1=0.f, a2=0.f, a3=0.f;
    for (int k0 = 0; k0 < 128; k0 += 32) {
        { int e = tid & 31, r = tid >> 5;
          #pragma unroll
          for (int i = 0; i < 4; i++) { int rr = r + i*4; As[rr][e] = g_slots[(m0+rr)*256 + kb + k0 + e]; } }
        { int c = tid & 31, e = tid >> 5;
          #pragma unroll
          for (int i = 0; i < 8; i++) { int ee = e + i*4; Bs[ee][c] = g_Mcomb[(size_t)(kb+k0+ee)*1024 + c0 + c]; } }
        __syncthreads();
        #pragma unroll
        for (int e = 0; e < 32; e++) {
            float a = As[row][e];
            float4 b4 = *(const float4*)&Bs[e][cg*4];
            a0 = fmaf(a,b4.x,a0); a1 = fmaf(a,b4.y,a1); a2 = fmaf(a,b4.z,a2); a3 = fmaf(a,b4.w,a3);
        }
        __syncthreads();
    }
    int cb = c0 + cg*4;
    if (blockIdx.z == 0) {
        #pragma unroll
        for (int p = 0; p < 8; p++) {
            const float* bp = g_cpart + p * 1024;
            a0 += bp[cb]; a1 += bp[cb+1]; a2 += bp[cb+2]; a3 += bp[cb+3];
        }
    }
    *(float4*)&g_qtgh2[(size_t)blockIdx.z*QT_PLANE + (m0+row)*1024 + cb] = make_float4(a0,a1,a2,a3);
}

// scores + chunk-local softmax stats.  grid (16 nchunk, 16 b), 256 thr.
__global__ void scores_kernel(const float* __restrict__ H, int t)
{
    __shared__ __align__(16) float4 Qs4[8][64];
    __shared__ float Hs[64][68];
    __shared__ float redM[8][2], redS[8][2], mrow[8];
    const int b = blockIdx.y, chunk = blockIdx.x;
    const int n0 = chunk * 64;
    const int tid = threadIdx.x;
    const int nl = tid & 63, sg = tid >> 6;          // sg 0..3, 2 slots each
    const int w = tid >> 5, lane = tid & 31;

    for (int i = tid; i < 512; i += 256) {
        int s = i >> 6, d4 = i & 63;
        float4 x0 = ((const float4*)(g_qtgh2 + (size_t)(b*8+s)*1024))[d4];
        float4 x1 = ((const float4*)(g_qtgh2 + QT_PLANE + (size_t)(b*8+s)*1024))[d4];
        Qs4[s][d4] = make_float4(x0.x+x1.x, x0.y+x1.y, x0.z+x1.z, x0.w+x1.w);
    }
    const float* hb = H + ((size_t)(b*16 + t) * 1024 + n0) * 256;
    float a[2] = {0.f, 0.f};
    for (int d0 = 0; d0 < 256; d0 += 64) {
        __syncthreads();
        { int c = tid & 63, r0 = tid >> 6;
          #pragma unroll
          for (int i = 0; i < 16; i++) Hs[r0 + i*4][c] = hb[(size_t)(r0 + i*4)*256 + d0 + c]; }
        __syncthreads();
        #pragma unroll
        for (int d = 0; d < 64; d += 4) {
            float4 h4 = *(const float4*)&Hs[nl][d];
            int qd = (d0 + d) >> 2;
            #pragma unroll
            for (int i = 0; i < 2; i++) {
                float4 q4 = Qs4[sg*2 + i][qd];
                a[i] = fmaf(h4.x,q4.x,a[i]); a[i] = fmaf(h4.y,q4.y,a[i]);
                a[i] = fmaf(h4.z,q4.z,a[i]); a[i] = fmaf(h4.w,q4.w,a[i]);
            }
        }
    }
    #pragma unroll
    for (int i = 0; i < 2; i++) {
        float m = a[i];
        #pragma unroll
        for (int o = 16; o > 0; o >>= 1) m = fmaxf(m, __shfl_xor_sync(0xffffffffu, m, o));
        if (lane == 0) redM[sg*2 + i][w & 1] = m;
    }
    __syncthreads();
    if (tid < 8) {
        float m = fmaxf(redM[tid][0], redM[tid][1]);
        mrow[tid] = m;
        g_pmax[(b*8 + tid) * 16 + chunk] = m;
    }
    __syncthreads();
    #pragma unroll
    for (int i = 0; i < 2; i++) {
        float e = expf(a[i] - mrow[sg*2 + i]);
        g_escore[(size_t)(b*8 + sg*2 + i) * 1024 + n0 + nl] = e;
        #pragma unroll
        for (int o = 16; o > 0; o >>= 1) e += __shfl_xor_sync(0xffffffffu, e, o);
        if (lane == 0) redS[sg*2 + i][w & 1] = e;
    }
    __syncthreads();
    if (tid < 8) g_psum[(b*8 + tid) * 16 + chunk] = redS[tid][0] + redS[tid][1];
}

// exact-normalized attn + Beta write + attn@H chunk partials.
// grid (16 nchunk, 16 b, 2 jhalf), 256 thr.
__global__ void u_kernel(const float* __restrict__ H, float* __restrict__ beta, int t)
{
    __shared__ float attnS[8][64];
    __shared__ float wrow[8];
    const int b = blockIdx.y, chunk = blockIdx.x, jh = blockIdx.z;
    const int n0 = chunk * 64, j0 = jh * 128;
    const int tid = threadIdx.x;

    if (tid < 8) {
        int r = b * 8 + tid;
        float m = g_pmax[r*16];
        #pragma unroll
        for (int c = 1; c < 16; c++) m = fmaxf(m, g_pmax[r*16 + c]);
        float S = 0.f;
        #pragma unroll
        for (int c = 0; c < 16; c++) S += g_psum[r*16 + c] * expf(g_pmax[r*16 + c] - m);
        wrow[tid] = expf(g_pmax[r*16 + chunk] - m) / S;
    }
    __syncthreads();
    for (int i = tid; i < 512; i += 256) {
        int s = i >> 6, n = i & 63;
        float aa = g_escore[(size_t)(b*8 + s) * 1024 + n0 + n] * wrow[s];
        attnS[s][n] = aa;
        if (jh == 0)
            beta[(size_t)((b*16 + t) * 8 + s) * 1024 + n0 + n] = aa;
    }
    __syncthreads();
    const int jj = tid & 127, sg = tid >> 7;
    const float* hb = H + ((size_t)(b*16 + t) * 1024 + n0) * 256 + j0 + jj;
    float acc[4] = {0.f, 0.f, 0.f, 0.f};
    #pragma unroll 8
    for (int n = 0; n < 64; n++) {
        float hv = hb[(size_t)n * 256];
        #pragma unroll
        for (int i = 0; i < 4; i++) acc[i] = fmaf(attnS[sg*4 + i][n], hv, acc[i]);
    }
    float* up = g_upart + (size_t)chunk * UP_PLANE;
    #pragma unroll
    for (int i = 0; i < 4; i++) up[(b*8 + sg*4 + i) * 256 + j0 + jj] = acc[i];
}

// U = sum of 16 chunk partials.  grid 32, 256 thr, float4.
__global__ void ucomb_kernel()
{
    int i4 = blockIdx.x * 256 + threadIdx.x;    // 0..8191
    float4 s = make_float4(0.f, 0.f, 0.f, 0.f);
    #pragma unroll
    for (int c = 0; c < 16; c++) {
        float4 v = ((const float4*)g_upart)[(size_t)c * (UP_PLANE/4) + i4];
        s.x += v.x; s.y += v.y; s.z += v.z; s.w += v.w;
    }
    ((float4*)g_U)[i4] = s;
}

// gi partials: U @ M2^T (+c2 on ks0).  grid (24 colT, 8 rowT, 2 ks), 128 thr, tile 16x32.
__global__ void k_gi()
{
    __shared__ float As[16][33];
    __shared__ __align__(16) float Bs[32][36];
    const int tid = threadIdx.x;
    const int m0 = blockIdx.y * 16, c0 = blockIdx.x * 32, kb = blockIdx.z * 128;
    const int row = tid & 15, cg = tid >> 4;
    float a0=0.f, a1=0.f, a2=0.f, a3=0.f;
    for (int k0 = 0; k0 < 128; k0 += 32) {
        { int e = tid & 31, r = tid >> 5;
          #pragma unroll
          for (int i = 0; i < 4; i++) { int rr = r + i*4; As[rr][e] = g_U[(m0+rr)*256 + kb + k0 + e]; } }
        { int e = tid & 31, c = tid >> 5;
          #pragma unroll
          for (int i = 0; i < 8; i++) { int cc = c + i*4; Bs[e][cc] = g_M2[(size_t)(c0+cc)*256 + kb + k0 + e]; } }
        __syncthreads();
        #pragma unroll
        for (int e = 0; e < 32; e++) {
            float a = As[row][e];
            float4 b4 = *(const float4*)&Bs[e][cg*4];
            a0 = fmaf(a,b4.x,a0); a1 = fmaf(a,b4.y,a1); a2 = fmaf(a,b4.z,a2); a3 = fmaf(a,b4.w,a3);
        }
        __syncthreads();
    }
    int cb = c0 + cg*4;
    if (blockIdx.z == 0) {
        #pragma unroll
        for (int p = 0; p < 8; p++) {
            const float* bp = g_c2part + p * 768;
            a0 += bp[cb]; a1 += bp[cb+1]; a2 += bp[cb+2]; a3 += bp[cb+3];
        }
    }
    *(float4*)&g_gi2[(size_t)blockIdx.z*GI_PLANE + (m0+row)*768 + cb] = make_float4(a0,a1,a2,a3);
}

// ffn1 with fused GRU (A-tile = s2 computed on the fly).  grid (8 colT, 8 rowT, 2 ks), 128 thr.
// Writes pre-activation partials (bias on ks0; ReLU applied at consumer after summing).
__global__ void ffn1_gru_kernel(const float* __restrict__ W1, const float* __restrict__ b1)
{
    __shared__ float As[16][33];
    __shared__ __align__(16) float Bs[32][36];
    const int tid = threadIdx.x;
    const int m0 = blockIdx.y * 16, c0 = blockIdx.x * 32, kb = blockIdx.z * 128;
    const int row = tid & 15, cg = tid >> 4;
    float a0=0.f, a1=0.f, a2=0.f, a3=0.f;
    for (int k0 = 0; k0 < 128; k0 += 32) {
        { int e = tid & 31, r = tid >> 5;
          #pragma unroll
          for (int i = 0; i < 4; i++) {
              int rr = r + i*4, g = m0 + rr, d = kb + k0 + e;
              float gir = g_gi2[g*768 + d]       + g_gi2[GI_PLANE + g*768 + d];
              float giz = g_gi2[g*768 + 256 + d] + g_gi2[GI_PLANE + g*768 + 256 + d];
              float gin = g_gi2[g*768 + 512 + d] + g_gi2[GI_PLANE + g*768 + 512 + d];
              float ghr = g_qtgh2[g*1024 + 256 + d] + g_qtgh2[QT_PLANE + g*1024 + 256 + d];
              float ghz = g_qtgh2[g*1024 + 512 + d] + g_qtgh2[QT_PLANE + g*1024 + 512 + d];
              float ghn = g_qtgh2[g*1024 + 768 + d] + g_qtgh2[QT_PLANE + g*1024 + 768 + d];
              float rg = sigm(gir + ghr);
              float z  = sigm(giz + ghz);
              float nn = tanhf(gin + rg * ghn);
              float s2 = (1.f - z) * nn + z * g_slots[g*256 + d];
              As[rr][e] = s2;
              if (blockIdx.x == 0) g_s2[g*256 + d] = s2;
          } }
        { int e = tid & 31, c = tid >> 5;
          #pragma unroll
          for (int i = 0; i < 8; i++) { int cc = c + i*4; Bs[e][cc] = W1[(size_t)(c0+cc)*256 + kb + k0 + e]; } }
        __syncthreads();
        #pragma unroll
        for (int e = 0; e < 32; e++) {
            float a = As[row][e];
            float4 b4 = *(const float4*)&Bs[e][cg*4];
            a0 = fmaf(a,b4.x,a0); a1 = fmaf(a,b4.y,a1); a2 = fmaf(a,b4.z,a2); a3 = fmaf(a,b4.w,a3);
        }
        __syncthreads();
    }
    int cb = c0 + cg*4;
    if (blockIdx.z == 0) { a0 += b1[cb]; a1 += b1[cb+1]; a2 += b1[cb+2]; a3 += b1[cb+3]; }
    *(float4*)&g_h1p[(size_t)blockIdx.z*H1_PLANE + (m0+row)*256 + cb] = make_float4(a0,a1,a2,a3);
}

// ffn2 + residual + LayerNorm.  grid 32 (4 rows each), 256 thr; 2 warps per row.
__global__ void ffn2_ln_kernel(const float* __restrict__ W2, const float* __restrict__ b2,
                               const float* __restrict__ lg, const float* __restrict__ lb,
                               float* __restrict__ outS, int t)
{
    __shared__ float As[4][256];
    __shared__ float Bs[256 * 33];
    __shared__ float rs[4][2], rq[4][2];
    const int tid = threadIdx.x;
    const int w = tid >> 5, lane = tid & 31;
    const int rr = w >> 1, h = w & 1;
    const int r0 = blockIdx.x * 4, row = r0 + rr;

    for (int i = tid; i < 1024; i += 256) {
        int rj = i >> 8, k = i & 255;
        float v = g_h1p[(r0 + rj)*256 + k] + g_h1p[H1_PLANE + (r0 + rj)*256 + k];
        As[rj][k] = fmaxf(v, 0.f);
    }
    float acc[4] = {0.f, 0.f, 0.f, 0.f};
    for (int e0 = 0; e0 < 256; e0 += 32) {
        __syncthreads();
        for (int idx = tid; idx < 8192; idx += 256) {
            int c = idx >> 5, e = idx & 31;
            Bs[c * 33 + e] = W2[(size_t)c * 256 + e0 + e];
        }
        __syncthreads();
        #pragma unroll
        for (int e = 0; e < 32; e++) {
            float a = As[rr][e0 + e];
            #pragma unroll
            for (int i = 0; i < 4; i++)
                acc[i] = fmaf(a, Bs[(h*128 + lane + 32*i) * 33 + e], acc[i]);
        }
    }
    float x[4], s = 0.f, q = 0.f;
    #pragma unroll
    for (int i = 0; i < 4; i++) {
        int c = h*128 + lane + 32*i;
        x[i] = acc[i] + b2[c] + g_s2[(size_t)row * 256 + c];
        s += x[i]; q += x[i] * x[i];
    }
    #pragma unroll
    for (int o = 16; o > 0; o >>= 1) {
        s += __shfl_xor_sync(0xffffffffu, s, o);
        q += __shfl_xor_sync(0xffffffffu, q, o);
    }
    if (lane == 0) { rs[rr][h] = s; rq[rr][h] = q; }
    __syncthreads();
    s = rs[rr][0] + rs[rr][1];
    q = rq[rr][0] + rq[rr][1];
    float mean = s * (1.f/256.f);
    float var  = q * (1.f/256.f) - mean * mean;
    float inv  = rsqrtf(var + 1e-5f);
    int b = row >> 3, l = row & 7;
    float* oS = outS + (size_t)((b*16 + t) * 8 + l) * 256;
    #pragma unroll
    for (int i = 0; i < 4; i++) {
        int c = h*128 + lane + 32*i;
        float y = (x[i] - mean) * inv * lg[c] + lb[c];
        g_slots[(size_t)row * 256 + c] = y;
        oS[c] = y;
    }
}

// ================= launcher =================
extern "C" void kernel_launch(void* const* d_in, const int* in_sizes, int n_in,
                              void* d_out, int out_size)
{
    const float* H    = (const float*)d_in[0];
    const float* eps  = (const float*)d_in[1];
    const float* mu   = (const float*)d_in[2];
    const float* ls   = (const float*)d_in[3];
    const float* Wq   = (const float*)d_in[4];
    const float* bq   = (const float*)d_in[5];
    const float* Wk   = (const float*)d_in[6];
    // d_in[7] = bk: row-constant in logits, cancels in softmax — provably unused.
    const float* Wv   = (const float*)d_in[8];
    const float* bv   = (const float*)d_in[9];
    const float* W_ih = (const float*)d_in[10];
    const float* b_ih = (const float*)d_in[11];
    const float* W_hh = (const float*)d_in[12];
    const float* b_hh = (const float*)d_in[13];
    const float* W1   = (const float*)d_in[14];
    const float* b1   = (const float*)d_in[15];
    const float* W2   = (const float*)d_in[16];
    const float* b2   = (const float*)d_in[17];
    const float* lng  = (const float*)d_in[18];
    const float* lnb  = (const float*)d_in[19];

    float* outS = (float*)d_out;
    float* outB = outS + S_ELEMS;

    pre_misc<<<952, 256>>>(eps, mu, ls, W_hh, bq, Wk, b_hh, W_ih, bv, b_ih);
    pre_gemm<<<dim3(8, 32), 256>>>(Wq, Wk, W_ih, Wv);

    for (int t = 0; t < 16; t++) {
        k_qtgh<<<dim3(32, 8, 2), 128>>>();
        scores_kernel<<<dim3(16, 16), 256>>>(H, t);
        u_kernel<<<dim3(16, 16, 2), 256>>>(H, outB, t);
        ucomb_kernel<<<32, 256>>>();
        k_gi<<<dim3(24, 8, 2), 128>>>();
        ffn1_gru_kernel<<<dim3(8, 8, 2), 128>>>(W1, b1);
        ffn2_ln_kernel<<<32, 256>>>(W2, b2, lng, lnb, outS, t);
    }
}